// round 1
// baseline (speedup 1.0000x reference)
#include <cuda_runtime.h>
#include <cuda_bf16.h>

#define N_NODES 50000
#define N_EDGES 1250000
#define HID 64
#define CDIM 128   // 2*HID

// ---------------------------------------------------------------------------
// Kernel 1: initialize combined = [x | 0]   (combined lives inside d_out)
// One thread per float4. combined row = 128 floats = 32 float4; first 16 = x.
// ---------------------------------------------------------------------------
__global__ void init_combined_kernel(const float4* __restrict__ x4,
                                     float4* __restrict__ comb4) {
    int idx = blockIdx.x * blockDim.x + threadIdx.x;   // over N_NODES*32
    if (idx >= N_NODES * 32) return;
    int node = idx >> 5;
    int q    = idx & 31;
    float4 v;
    if (q < 16) {
        v = __ldg(x4 + node * 16 + q);
    } else {
        v = make_float4(0.f, 0.f, 0.f, 0.f);
    }
    comb4[idx] = v;
}

// ---------------------------------------------------------------------------
// Kernel 2: scatter-add edge_attr into combined[:, 64:128] with vector
// reductions. One thread per (edge, 4-feature group): 16 threads/edge.
// red.global.add.v4.f32 -> 4x fewer L2 atomic slots than scalar.
// ---------------------------------------------------------------------------
__global__ void scatter_kernel(const int* __restrict__ row,
                               const float4* __restrict__ attr4,
                               float* __restrict__ combined) {
    long long idx = (long long)blockIdx.x * blockDim.x + threadIdx.x;
    if (idx >= (long long)N_EDGES * 16) return;
    int e = (int)(idx >> 4);
    int g = (int)(idx & 15);
    int r = __ldg(row + e);
    float4 v = __ldg(attr4 + idx);            // attr4[e*16 + g] == attr4[idx]
    float* dst = combined + (size_t)r * CDIM + HID + g * 4;
    asm volatile("red.global.add.v4.f32 [%0], {%1, %2, %3, %4};"
                 :: "l"(dst), "f"(v.x), "f"(v.y), "f"(v.z), "f"(v.w)
                 : "memory");
}

// ---------------------------------------------------------------------------
// Kernel 3: MLP.  out = silu(combined @ W1 + b1) @ W2 + b2
// 256 threads/block = 4 groups of 64; each group handles one node per tile.
// Weights staged in dynamic smem once per block; few persistent blocks so
// weight traffic is negligible. Thread j computes feature j.
// ---------------------------------------------------------------------------
__global__ void mlp_kernel(const float* __restrict__ combined,
                           const float* __restrict__ W1,
                           const float* __restrict__ b1,
                           const float* __restrict__ W2,
                           const float* __restrict__ b2,
                           float* __restrict__ out) {
    extern __shared__ float smem[];
    float* sW1 = smem;                    // 128*64
    float* sW2 = sW1 + CDIM * HID;        // 64*64
    float* sb1 = sW2 + HID * HID;         // 64
    float* sb2 = sb1 + HID;               // 64
    float* sc  = sb2 + HID;               // 4*128
    float* sh  = sc + 4 * CDIM;           // 4*64

    int tid = threadIdx.x;

    // stage weights
    for (int i = tid; i < CDIM * HID; i += blockDim.x) sW1[i] = W1[i];
    for (int i = tid; i < HID * HID;  i += blockDim.x) sW2[i] = W2[i];
    if (tid < HID) { sb1[tid] = b1[tid]; sb2[tid] = b2[tid]; }
    __syncthreads();

    int g = tid >> 6;          // group 0..3
    int j = tid & 63;          // output feature

    // grid-stride over tiles of 4 nodes
    int n_tiles = (N_NODES + 3) / 4;
    for (int tile = blockIdx.x; tile < n_tiles; tile += gridDim.x) {
        int node0 = tile * 4;

        // stage 4 node rows of combined (512 consecutive floats)
        for (int i = tid; i < 4 * CDIM; i += blockDim.x) {
            int n = node0 + (i >> 7);
            sc[i] = (n < N_NODES) ? combined[(size_t)node0 * CDIM + i] : 0.f;
        }
        __syncthreads();

        int node = node0 + g;
        float acc = sb1[j];
        const float* c = sc + g * CDIM;
        #pragma unroll
        for (int i = 0; i < CDIM; i++) {
            acc = fmaf(c[i], sW1[i * HID + j], acc);
        }
        // silu
        float h = acc / (1.0f + __expf(-acc));
        sh[g * HID + j] = h;
        __syncthreads();

        float acc2 = sb2[j];
        const float* hh = sh + g * HID;
        #pragma unroll
        for (int k = 0; k < HID; k++) {
            acc2 = fmaf(hh[k], sW2[k * HID + j], acc2);
        }
        if (node < N_NODES) {
            out[(size_t)node * HID + j] = acc2;
        }
        __syncthreads();   // protect sc/sh before next tile
    }
}

// ---------------------------------------------------------------------------
extern "C" void kernel_launch(void* const* d_in, const int* in_sizes, int n_in,
                              void* d_out, int out_size) {
    const int*   edge_index = (const int*)d_in[0];   // [2, N_EDGES]
    const float* edge_attr  = (const float*)d_in[1]; // [N_EDGES, 64]
    const float* x          = (const float*)d_in[2]; // [N_NODES, 64]
    const float* W1         = (const float*)d_in[3]; // [128, 64]
    const float* b1         = (const float*)d_in[4]; // [64]
    const float* W2         = (const float*)d_in[5]; // [64, 64]
    const float* b2         = (const float*)d_in[6]; // [64]

    float* out      = (float*)d_out;                 // [N_NODES, 64]
    float* combined = out + (size_t)N_NODES * HID;   // [N_NODES, 128]

    // 1) combined = [x | 0]
    {
        int total = N_NODES * 32;
        int threads = 256;
        init_combined_kernel<<<(total + threads - 1) / threads, threads>>>(
            (const float4*)x, (float4*)combined);
    }

    // 2) scatter-add edges into combined[:, 64:128]
    {
        long long total = (long long)N_EDGES * 16;
        int threads = 256;
        int blocks = (int)((total + threads - 1) / threads);
        scatter_kernel<<<blocks, threads>>>(
            edge_index /* row = first N_EDGES ints */,
            (const float4*)edge_attr, combined);
    }

    // 3) MLP
    {
        int smem_bytes = (CDIM * HID + HID * HID + 2 * HID + 4 * CDIM + 4 * HID)
                         * (int)sizeof(float);
        cudaFuncSetAttribute(mlp_kernel,
                             cudaFuncAttributeMaxDynamicSharedMemorySize,
                             smem_bytes);
        mlp_kernel<<<592, 256, smem_bytes>>>(combined, W1, b1, W2, b2, out);
    }
}